// round 2
// baseline (speedup 1.0000x reference)
#include <cuda_runtime.h>
#include <cstdint>

// Problem constants (fixed by the reference)
#define N_SRC   100000
#define N_DST   100000
#define N_EDGES 3200000
#define OUT_DIM 64

// ---------------------------------------------------------------------------
// Static device scratch (allocation-free per harness rules)
// ---------------------------------------------------------------------------
__device__ float g_feat[(size_t)N_SRC * OUT_DIM];   // 25.6 MB: weight[node_ids]*cj
__device__ int   g_counts[N_DST];                   // per-dst edge counts
__device__ int   g_offsets[N_DST + 1];              // CSR row offsets
__device__ int   g_cursor[N_DST];                   // scatter cursors
__device__ int   g_sorted_src[N_EDGES];             // src idx bucketed by dst

// ---------------------------------------------------------------------------
// Kernel 1: feat = weight[node_ids] * cj   (float4 per thread)
// ---------------------------------------------------------------------------
__global__ void prep_feat_kernel(const int* __restrict__ node_ids,
                                 const float* __restrict__ cj,
                                 const float* __restrict__ weight) {
    int t = blockIdx.x * blockDim.x + threadIdx.x;
    if (t >= N_SRC * (OUT_DIM / 4)) return;
    int i = t >> 4;
    int c = t & 15;
    int nid = node_ids[i];
    float s = cj[i];
    float4 v = reinterpret_cast<const float4*>(weight + (size_t)nid * OUT_DIM)[c];
    v.x *= s; v.y *= s; v.z *= s; v.w *= s;
    reinterpret_cast<float4*>(g_feat + (size_t)i * OUT_DIM)[c] = v;
}

// ---------------------------------------------------------------------------
// Kernel 2: zero histogram counters
// ---------------------------------------------------------------------------
__global__ void zero_counts_kernel() {
    int t = blockIdx.x * blockDim.x + threadIdx.x;
    if (t < N_DST) g_counts[t] = 0;
}

// ---------------------------------------------------------------------------
// Kernel 3: histogram of dst degrees (no-return int reductions)
// ---------------------------------------------------------------------------
__global__ void hist_kernel(const int* __restrict__ dst_idx) {
    int t = blockIdx.x * blockDim.x + threadIdx.x;
    if (t < N_EDGES) atomicAdd(&g_counts[dst_idx[t]], 1);
}

// ---------------------------------------------------------------------------
// Kernel 4: exclusive scan over counts (single block, 1024 threads,
// 98 elements serially per thread + Hillis-Steele block scan)
// ---------------------------------------------------------------------------
__global__ void scan_kernel() {
    const int T = 1024;
    const int CHUNK = (N_DST + T - 1) / T;   // 98
    __shared__ int sh[T];
    int tid = threadIdx.x;
    int base = tid * CHUNK;

    // pass 1: thread-local total
    int total = 0;
    #pragma unroll 4
    for (int k = 0; k < CHUNK; k++) {
        int i = base + k;
        if (i < N_DST) total += g_counts[i];
    }
    sh[tid] = total;
    __syncthreads();

    // inclusive block scan
    for (int off = 1; off < T; off <<= 1) {
        int v = (tid >= off) ? sh[tid - off] : 0;
        __syncthreads();
        sh[tid] += v;
        __syncthreads();
    }
    int excl = sh[tid] - total;

    if (tid == 0) g_offsets[N_DST] = sh[T - 1];  // grand total = N_EDGES

    // pass 2: write per-element exclusive offsets + cursors
    int run = excl;
    for (int k = 0; k < CHUNK; k++) {
        int i = base + k;
        if (i < N_DST) {
            g_offsets[i] = run;
            g_cursor[i]  = run;
            run += g_counts[i];
        }
    }
}

// ---------------------------------------------------------------------------
// Kernel 5: permute src indices into dst buckets
// ---------------------------------------------------------------------------
__global__ void permute_kernel(const int* __restrict__ src_idx,
                               const int* __restrict__ dst_idx) {
    int t = blockIdx.x * blockDim.x + threadIdx.x;
    if (t >= N_EDGES) return;
    int d = dst_idx[t];
    int pos = atomicAdd(&g_cursor[d], 1);
    g_sorted_src[pos] = src_idx[t];
}

// ---------------------------------------------------------------------------
// Kernel 6: pull-style accumulate. 16 threads per dst row, one float4 lane
// each. Registers accumulate; exactly one 256B store per dst. ci folded in.
// 4x-unrolled index prefetch for memory-level parallelism.
// ---------------------------------------------------------------------------
__global__ void accumulate_kernel(const float* __restrict__ ci,
                                  float* __restrict__ out) {
    int t = blockIdx.x * blockDim.x + threadIdx.x;
    int d = t >> 4;
    int c = t & 15;
    if (d >= N_DST) return;

    int beg = g_offsets[d];
    int end = g_offsets[d + 1];

    float4 acc = make_float4(0.f, 0.f, 0.f, 0.f);

    int j = beg;
    for (; j + 4 <= end; j += 4) {
        int s0 = g_sorted_src[j + 0];
        int s1 = g_sorted_src[j + 1];
        int s2 = g_sorted_src[j + 2];
        int s3 = g_sorted_src[j + 3];
        float4 v0 = reinterpret_cast<const float4*>(g_feat + (size_t)s0 * OUT_DIM)[c];
        float4 v1 = reinterpret_cast<const float4*>(g_feat + (size_t)s1 * OUT_DIM)[c];
        float4 v2 = reinterpret_cast<const float4*>(g_feat + (size_t)s2 * OUT_DIM)[c];
        float4 v3 = reinterpret_cast<const float4*>(g_feat + (size_t)s3 * OUT_DIM)[c];
        acc.x += v0.x; acc.y += v0.y; acc.z += v0.z; acc.w += v0.w;
        acc.x += v1.x; acc.y += v1.y; acc.z += v1.z; acc.w += v1.w;
        acc.x += v2.x; acc.y += v2.y; acc.z += v2.z; acc.w += v2.w;
        acc.x += v3.x; acc.y += v3.y; acc.z += v3.z; acc.w += v3.w;
    }
    for (; j < end; j++) {
        int s = g_sorted_src[j];
        float4 v = reinterpret_cast<const float4*>(g_feat + (size_t)s * OUT_DIM)[c];
        acc.x += v.x; acc.y += v.y; acc.z += v.z; acc.w += v.w;
    }

    float sc = ci[d];
    acc.x *= sc; acc.y *= sc; acc.z *= sc; acc.w *= sc;
    reinterpret_cast<float4*>(out + (size_t)d * OUT_DIM)[c] = acc;
}

// ---------------------------------------------------------------------------
// Launch. Input order per metadata: node_ids, src_idx, dst_idx, cj, ci, weight
// ---------------------------------------------------------------------------
extern "C" void kernel_launch(void* const* d_in, const int* in_sizes, int n_in,
                              void* d_out, int out_size) {
    const int*   node_ids = (const int*)  d_in[0];
    const int*   src_idx  = (const int*)  d_in[1];
    const int*   dst_idx  = (const int*)  d_in[2];
    const float* cj       = (const float*)d_in[3];
    const float* ci       = (const float*)d_in[4];
    const float* weight   = (const float*)d_in[5];
    float*       out      = (float*)      d_out;

    const int THREADS = 256;

    // 1) feat = weight[node_ids] * cj
    {
        int n = N_SRC * (OUT_DIM / 4);
        prep_feat_kernel<<<(n + THREADS - 1) / THREADS, THREADS>>>(node_ids, cj, weight);
    }
    // 2) zero counters
    zero_counts_kernel<<<(N_DST + THREADS - 1) / THREADS, THREADS>>>();
    // 3) histogram
    hist_kernel<<<(N_EDGES + THREADS - 1) / THREADS, THREADS>>>(dst_idx);
    // 4) scan
    scan_kernel<<<1, 1024>>>();
    // 5) permute src by dst bucket
    permute_kernel<<<(N_EDGES + THREADS - 1) / THREADS, THREADS>>>(src_idx, dst_idx);
    // 6) accumulate + ci scale + store
    {
        int n = N_DST * 16;
        accumulate_kernel<<<(n + THREADS - 1) / THREADS, THREADS>>>(ci, out);
    }
}

// round 3
// speedup vs baseline: 2.2007x; 2.2007x over previous
#include <cuda_runtime.h>
#include <cstdint>

// Problem constants (fixed by the reference)
#define N_SRC   100000
#define N_DST   100000
#define N_EDGES 3200000
#define OUT_DIM 64

#define SCAN_BLK 256
#define NUM_BLKS ((N_DST + SCAN_BLK - 1) / SCAN_BLK)   // 391

// ---------------------------------------------------------------------------
// Static device scratch (allocation-free per harness rules)
// ---------------------------------------------------------------------------
__device__ float g_feat[(size_t)N_SRC * OUT_DIM];   // 25.6 MB: weight[node_ids]*cj
__device__ int   g_counts[N_DST];                   // per-dst edge counts
__device__ int   g_offsets[N_DST + 1];              // CSR row offsets
__device__ int   g_cursor[N_DST];                   // scatter cursors
__device__ int   g_sorted_src[N_EDGES];             // src idx bucketed by dst
__device__ int   g_block_sums[512];                 // per-block partial sums

// ---------------------------------------------------------------------------
// Kernel 1: feat = weight[node_ids] * cj   (float4 per thread)
// ---------------------------------------------------------------------------
__global__ void prep_feat_kernel(const int* __restrict__ node_ids,
                                 const float* __restrict__ cj,
                                 const float* __restrict__ weight) {
    int t = blockIdx.x * blockDim.x + threadIdx.x;
    if (t >= N_SRC * (OUT_DIM / 4)) return;
    int i = t >> 4;
    int c = t & 15;
    int nid = node_ids[i];
    float s = cj[i];
    float4 v = reinterpret_cast<const float4*>(weight + (size_t)nid * OUT_DIM)[c];
    v.x *= s; v.y *= s; v.z *= s; v.w *= s;
    reinterpret_cast<float4*>(g_feat + (size_t)i * OUT_DIM)[c] = v;
}

// ---------------------------------------------------------------------------
// Kernel 2: zero histogram counters
// ---------------------------------------------------------------------------
__global__ void zero_counts_kernel() {
    int t = blockIdx.x * blockDim.x + threadIdx.x;
    if (t < N_DST) g_counts[t] = 0;
}

// ---------------------------------------------------------------------------
// Kernel 3: histogram of dst degrees
// ---------------------------------------------------------------------------
__global__ void hist_kernel(const int* __restrict__ dst_idx) {
    int t = blockIdx.x * blockDim.x + threadIdx.x;
    if (t < N_EDGES) atomicAdd(&g_counts[dst_idx[t]], 1);
}

// ---------------------------------------------------------------------------
// Kernel 4a: per-block partial sums of counts (391 blocks x 256)
// ---------------------------------------------------------------------------
__global__ void partial_sums_kernel() {
    __shared__ int ws[8];
    int b = blockIdx.x;
    int i = b * SCAN_BLK + threadIdx.x;
    int v = (i < N_DST) ? g_counts[i] : 0;
    #pragma unroll
    for (int off = 16; off; off >>= 1) v += __shfl_down_sync(0xffffffffu, v, off);
    if ((threadIdx.x & 31) == 0) ws[threadIdx.x >> 5] = v;
    __syncthreads();
    if (threadIdx.x < 8) {
        int s = ws[threadIdx.x];
        #pragma unroll
        for (int off = 4; off; off >>= 1) s += __shfl_down_sync(0xffu, s, off);
        if (threadIdx.x == 0) g_block_sums[b] = s;
    }
}

// ---------------------------------------------------------------------------
// Kernel 4b: exclusive scan of the 391 block sums (single block of 512)
// ---------------------------------------------------------------------------
__global__ void scan_sums_kernel() {
    __shared__ int sh[512];
    int tid = threadIdx.x;
    int v = (tid < NUM_BLKS) ? g_block_sums[tid] : 0;
    sh[tid] = v;
    __syncthreads();
    #pragma unroll
    for (int off = 1; off < 512; off <<= 1) {
        int y = (tid >= off) ? sh[tid - off] : 0;
        __syncthreads();
        sh[tid] += y;
        __syncthreads();
    }
    if (tid < NUM_BLKS) g_block_sums[tid] = sh[tid] - v;   // exclusive prefix
    if (tid == 0) g_offsets[N_DST] = sh[511];               // grand total
}

// ---------------------------------------------------------------------------
// Kernel 4c: per-element exclusive offsets = block-local scan + block prefix
// ---------------------------------------------------------------------------
__global__ void offsets_kernel() {
    __shared__ int ws[8];
    int b = blockIdx.x;
    int i = b * SCAN_BLK + threadIdx.x;
    int lane = threadIdx.x & 31;
    int w = threadIdx.x >> 5;

    int v = (i < N_DST) ? g_counts[i] : 0;
    int x = v;
    #pragma unroll
    for (int off = 1; off < 32; off <<= 1) {
        int y = __shfl_up_sync(0xffffffffu, x, off);
        if (lane >= off) x += y;
    }
    if (lane == 31) ws[w] = x;
    __syncthreads();
    if (w == 0) {
        int s = (lane < 8) ? ws[lane] : 0;
        #pragma unroll
        for (int off = 1; off < 8; off <<= 1) {
            int y = __shfl_up_sync(0xffffffffu, s, off);
            if (lane >= off) s += y;
        }
        if (lane < 8) ws[lane] = s;
    }
    __syncthreads();
    int excl = (x - v) + (w > 0 ? ws[w - 1] : 0) + g_block_sums[b];
    if (i < N_DST) {
        g_offsets[i] = excl;
        g_cursor[i]  = excl;
    }
}

// ---------------------------------------------------------------------------
// Kernel 5: permute src indices into dst buckets
// ---------------------------------------------------------------------------
__global__ void permute_kernel(const int* __restrict__ src_idx,
                               const int* __restrict__ dst_idx) {
    int t = blockIdx.x * blockDim.x + threadIdx.x;
    if (t >= N_EDGES) return;
    int d = dst_idx[t];
    int pos = atomicAdd(&g_cursor[d], 1);
    g_sorted_src[pos] = src_idx[t];
}

// ---------------------------------------------------------------------------
// Kernel 6: pull-style accumulate. 16 threads per dst row, one float4 lane
// each. Registers accumulate; exactly one 256B store per dst. ci folded in.
// ---------------------------------------------------------------------------
__global__ void accumulate_kernel(const float* __restrict__ ci,
                                  float* __restrict__ out) {
    int t = blockIdx.x * blockDim.x + threadIdx.x;
    int d = t >> 4;
    int c = t & 15;
    if (d >= N_DST) return;

    int beg = g_offsets[d];
    int end = g_offsets[d + 1];

    float4 acc = make_float4(0.f, 0.f, 0.f, 0.f);

    int j = beg;
    for (; j + 4 <= end; j += 4) {
        int s0 = g_sorted_src[j + 0];
        int s1 = g_sorted_src[j + 1];
        int s2 = g_sorted_src[j + 2];
        int s3 = g_sorted_src[j + 3];
        float4 v0 = reinterpret_cast<const float4*>(g_feat + (size_t)s0 * OUT_DIM)[c];
        float4 v1 = reinterpret_cast<const float4*>(g_feat + (size_t)s1 * OUT_DIM)[c];
        float4 v2 = reinterpret_cast<const float4*>(g_feat + (size_t)s2 * OUT_DIM)[c];
        float4 v3 = reinterpret_cast<const float4*>(g_feat + (size_t)s3 * OUT_DIM)[c];
        acc.x += v0.x; acc.y += v0.y; acc.z += v0.z; acc.w += v0.w;
        acc.x += v1.x; acc.y += v1.y; acc.z += v1.z; acc.w += v1.w;
        acc.x += v2.x; acc.y += v2.y; acc.z += v2.z; acc.w += v2.w;
        acc.x += v3.x; acc.y += v3.y; acc.z += v3.z; acc.w += v3.w;
    }
    for (; j < end; j++) {
        int s = g_sorted_src[j];
        float4 v = reinterpret_cast<const float4*>(g_feat + (size_t)s * OUT_DIM)[c];
        acc.x += v.x; acc.y += v.y; acc.z += v.z; acc.w += v.w;
    }

    float sc = ci[d];
    acc.x *= sc; acc.y *= sc; acc.z *= sc; acc.w *= sc;
    reinterpret_cast<float4*>(out + (size_t)d * OUT_DIM)[c] = acc;
}

// ---------------------------------------------------------------------------
// Launch. Input order per metadata: node_ids, src_idx, dst_idx, cj, ci, weight
// ---------------------------------------------------------------------------
extern "C" void kernel_launch(void* const* d_in, const int* in_sizes, int n_in,
                              void* d_out, int out_size) {
    const int*   node_ids = (const int*)  d_in[0];
    const int*   src_idx  = (const int*)  d_in[1];
    const int*   dst_idx  = (const int*)  d_in[2];
    const float* cj       = (const float*)d_in[3];
    const float* ci       = (const float*)d_in[4];
    const float* weight   = (const float*)d_in[5];
    float*       out      = (float*)      d_out;

    const int THREADS = 256;

    // 1) feat = weight[node_ids] * cj
    {
        int n = N_SRC * (OUT_DIM / 4);
        prep_feat_kernel<<<(n + THREADS - 1) / THREADS, THREADS>>>(node_ids, cj, weight);
    }
    // 2) zero counters
    zero_counts_kernel<<<(N_DST + THREADS - 1) / THREADS, THREADS>>>();
    // 3) histogram
    hist_kernel<<<(N_EDGES + THREADS - 1) / THREADS, THREADS>>>(dst_idx);
    // 4) three-phase exclusive scan (full-chip)
    partial_sums_kernel<<<NUM_BLKS, SCAN_BLK>>>();
    scan_sums_kernel<<<1, 512>>>();
    offsets_kernel<<<NUM_BLKS, SCAN_BLK>>>();
    // 5) permute src by dst bucket
    permute_kernel<<<(N_EDGES + THREADS - 1) / THREADS, THREADS>>>(src_idx, dst_idx);
    // 6) accumulate + ci scale + store
    {
        int n = N_DST * 16;
        accumulate_kernel<<<(n + THREADS - 1) / THREADS, THREADS>>>(ci, out);
    }
}

// round 5
// speedup vs baseline: 2.4343x; 1.1062x over previous
#include <cuda_runtime.h>
#include <cuda_fp16.h>
#include <cstdint>

// Problem constants (fixed by the reference)
#define N_SRC   100000
#define N_DST   100000
#define N_EDGES 3200000
#define OUT_DIM 64

#define SCAN_BLK 256
#define NUM_BLKS ((N_DST + SCAN_BLK - 1) / SCAN_BLK)   // 391

// ---------------------------------------------------------------------------
// Static device scratch (allocation-free per harness rules)
// ---------------------------------------------------------------------------
__device__ __half2 g_feat_h[(size_t)N_SRC * OUT_DIM / 2];  // 12.8 MB fp16 feat
__device__ int     g_counts[N_DST];                        // per-dst edge counts
__device__ int     g_offsets[N_DST + 1];                   // CSR row offsets
__device__ int     g_cursor[N_DST];                        // scatter cursors
__device__ int     g_sorted_src[N_EDGES];                  // src idx by dst bucket
__device__ int     g_block_sums[512];                      // per-block partial sums

// ---------------------------------------------------------------------------
// Kernel 1: feat_h = (half)(weight[node_ids] * cj). 8 threads/row, 16B each.
// ---------------------------------------------------------------------------
__global__ void prep_feat_kernel(const int* __restrict__ node_ids,
                                 const float* __restrict__ cj,
                                 const float* __restrict__ weight) {
    int t = blockIdx.x * blockDim.x + threadIdx.x;
    if (t >= N_SRC * 8) return;
    int i = t >> 3;          // row
    int c = t & 7;           // 8-half (16B) chunk within row
    int nid = node_ids[i];
    float s = cj[i];
    const float4* wrow = reinterpret_cast<const float4*>(weight + (size_t)nid * OUT_DIM);
    float4 a = wrow[c * 2 + 0];
    float4 b = wrow[c * 2 + 1];
    __half2 h[4];
    h[0] = __floats2half2_rn(a.x * s, a.y * s);
    h[1] = __floats2half2_rn(a.z * s, a.w * s);
    h[2] = __floats2half2_rn(b.x * s, b.y * s);
    h[3] = __floats2half2_rn(b.z * s, b.w * s);
    // 16-byte vector store of 4 __half2
    float4 packed = *reinterpret_cast<const float4*>(h);
    reinterpret_cast<float4*>(g_feat_h)[(size_t)i * 8 + c] = packed;
}

// ---------------------------------------------------------------------------
// Kernel 2: zero histogram counters
// ---------------------------------------------------------------------------
__global__ void zero_counts_kernel() {
    int t = blockIdx.x * blockDim.x + threadIdx.x;
    if (t < N_DST) g_counts[t] = 0;
}

// ---------------------------------------------------------------------------
// Kernel 3: histogram of dst degrees
// ---------------------------------------------------------------------------
__global__ void hist_kernel(const int* __restrict__ dst_idx) {
    int t = blockIdx.x * blockDim.x + threadIdx.x;
    if (t < N_EDGES) atomicAdd(&g_counts[dst_idx[t]], 1);
}

// ---------------------------------------------------------------------------
// Kernel 4a: per-block partial sums of counts (391 blocks x 256)
// ---------------------------------------------------------------------------
__global__ void partial_sums_kernel() {
    __shared__ int ws[8];
    int b = blockIdx.x;
    int i = b * SCAN_BLK + threadIdx.x;
    int v = (i < N_DST) ? g_counts[i] : 0;
    #pragma unroll
    for (int off = 16; off; off >>= 1) v += __shfl_down_sync(0xffffffffu, v, off);
    if ((threadIdx.x & 31) == 0) ws[threadIdx.x >> 5] = v;
    __syncthreads();
    if (threadIdx.x < 8) {
        int s = ws[threadIdx.x];
        #pragma unroll
        for (int off = 4; off; off >>= 1) s += __shfl_down_sync(0xffu, s, off);
        if (threadIdx.x == 0) g_block_sums[b] = s;
    }
}

// ---------------------------------------------------------------------------
// Kernel 4b: exclusive scan of the 391 block sums (single block of 512)
// ---------------------------------------------------------------------------
__global__ void scan_sums_kernel() {
    __shared__ int sh[512];
    int tid = threadIdx.x;
    int v = (tid < NUM_BLKS) ? g_block_sums[tid] : 0;
    sh[tid] = v;
    __syncthreads();
    #pragma unroll
    for (int off = 1; off < 512; off <<= 1) {
        int y = (tid >= off) ? sh[tid - off] : 0;
        __syncthreads();
        sh[tid] += y;
        __syncthreads();
    }
    if (tid < NUM_BLKS) g_block_sums[tid] = sh[tid] - v;   // exclusive prefix
    if (tid == 0) g_offsets[N_DST] = sh[511];               // grand total
}

// ---------------------------------------------------------------------------
// Kernel 4c: per-element exclusive offsets = block-local scan + block prefix
// ---------------------------------------------------------------------------
__global__ void offsets_kernel() {
    __shared__ int ws[8];
    int b = blockIdx.x;
    int i = b * SCAN_BLK + threadIdx.x;
    int lane = threadIdx.x & 31;
    int w = threadIdx.x >> 5;

    int v = (i < N_DST) ? g_counts[i] : 0;
    int x = v;
    #pragma unroll
    for (int off = 1; off < 32; off <<= 1) {
        int y = __shfl_up_sync(0xffffffffu, x, off);
        if (lane >= off) x += y;
    }
    if (lane == 31) ws[w] = x;
    __syncthreads();
    if (w == 0) {
        int s = (lane < 8) ? ws[lane] : 0;
        #pragma unroll
        for (int off = 1; off < 8; off <<= 1) {
            int y = __shfl_up_sync(0xffffffffu, s, off);
            if (lane >= off) s += y;
        }
        if (lane < 8) ws[lane] = s;
    }
    __syncthreads();
    int excl = (x - v) + (w > 0 ? ws[w - 1] : 0) + g_block_sums[b];
    if (i < N_DST) {
        g_offsets[i] = excl;
        g_cursor[i]  = excl;
    }
}

// ---------------------------------------------------------------------------
// Kernel 5: permute src indices into dst buckets
// ---------------------------------------------------------------------------
__global__ void permute_kernel(const int* __restrict__ src_idx,
                               const int* __restrict__ dst_idx) {
    int t = blockIdx.x * blockDim.x + threadIdx.x;
    if (t >= N_EDGES) return;
    int d = dst_idx[t];
    int pos = atomicAdd(&g_cursor[d], 1);
    g_sorted_src[pos] = src_idx[t];
}

// ---------------------------------------------------------------------------
// Kernel 6: pull-style accumulate over fp16 feat. 8 threads per dst row, one
// 16B (8-half) lane each -> 128B coalesced row read per edge. fp32
// accumulation in registers; ci folded into the two 16B stores per thread.
// ---------------------------------------------------------------------------
__global__ void accumulate_kernel(const float* __restrict__ ci,
                                  float* __restrict__ out) {
    int t = blockIdx.x * blockDim.x + threadIdx.x;
    int d = t >> 3;
    int c = t & 7;
    if (d >= N_DST) return;

    int beg = g_offsets[d];
    int end = g_offsets[d + 1];

    float a[8] = {0.f, 0.f, 0.f, 0.f, 0.f, 0.f, 0.f, 0.f};

    const float4* feat4 = reinterpret_cast<const float4*>(g_feat_h);

    int j = beg;
    for (; j + 4 <= end; j += 4) {
        int s0 = g_sorted_src[j + 0];
        int s1 = g_sorted_src[j + 1];
        int s2 = g_sorted_src[j + 2];
        int s3 = g_sorted_src[j + 3];
        float4 r[4];
        r[0] = feat4[(size_t)s0 * 8 + c];
        r[1] = feat4[(size_t)s1 * 8 + c];
        r[2] = feat4[(size_t)s2 * 8 + c];
        r[3] = feat4[(size_t)s3 * 8 + c];
        #pragma unroll
        for (int k = 0; k < 4; k++) {
            const __half2* hp = reinterpret_cast<const __half2*>(&r[k]);
            #pragma unroll
            for (int q = 0; q < 4; q++) {
                float2 f = __half22float2(hp[q]);
                a[q * 2 + 0] += f.x;
                a[q * 2 + 1] += f.y;
            }
        }
    }
    for (; j < end; j++) {
        int s = g_sorted_src[j];
        float4 r = feat4[(size_t)s * 8 + c];
        const __half2* hp = reinterpret_cast<const __half2*>(&r);
        #pragma unroll
        for (int q = 0; q < 4; q++) {
            float2 f = __half22float2(hp[q]);
            a[q * 2 + 0] += f.x;
            a[q * 2 + 1] += f.y;
        }
    }

    float sc = ci[d];
    float4 o0 = make_float4(a[0] * sc, a[1] * sc, a[2] * sc, a[3] * sc);
    float4 o1 = make_float4(a[4] * sc, a[5] * sc, a[6] * sc, a[7] * sc);
    float4* op = reinterpret_cast<float4*>(out + (size_t)d * OUT_DIM + c * 8);
    op[0] = o0;
    op[1] = o1;
}

// ---------------------------------------------------------------------------
// Launch. Input order per metadata: node_ids, src_idx, dst_idx, cj, ci, weight
// ---------------------------------------------------------------------------
extern "C" void kernel_launch(void* const* d_in, const int* in_sizes, int n_in,
                              void* d_out, int out_size) {
    const int*   node_ids = (const int*)  d_in[0];
    const int*   src_idx  = (const int*)  d_in[1];
    const int*   dst_idx  = (const int*)  d_in[2];
    const float* cj       = (const float*)d_in[3];
    const float* ci       = (const float*)d_in[4];
    const float* weight   = (const float*)d_in[5];
    float*       out      = (float*)      d_out;

    const int THREADS = 256;

    // 1) feat_h = (half)(weight[node_ids] * cj)
    {
        int n = N_SRC * 8;
        prep_feat_kernel<<<(n + THREADS - 1) / THREADS, THREADS>>>(node_ids, cj, weight);
    }
    // 2) zero counters
    zero_counts_kernel<<<(N_DST + THREADS - 1) / THREADS, THREADS>>>();
    // 3) histogram
    hist_kernel<<<(N_EDGES + THREADS - 1) / THREADS, THREADS>>>(dst_idx);
    // 4) three-phase exclusive scan (full-chip)
    partial_sums_kernel<<<NUM_BLKS, SCAN_BLK>>>();
    scan_sums_kernel<<<1, 512>>>();
    offsets_kernel<<<NUM_BLKS, SCAN_BLK>>>();
    // 5) permute src by dst bucket
    permute_kernel<<<(N_EDGES + THREADS - 1) / THREADS, THREADS>>>(src_idx, dst_idx);
    // 6) accumulate + ci scale + store
    {
        int n = N_DST * 8;
        accumulate_kernel<<<(n + THREADS - 1) / THREADS, THREADS>>>(ci, out);
    }
}